// round 4
// baseline (speedup 1.0000x reference)
#include <cuda_runtime.h>
#include <cuda_bf16.h>
#include <stdint.h>

#define NSPK 256
#define MUTT 64
#define DDIM 1024
#define NROWS (NSPK*MUTT)   // 16384

// ---------------- device scratch (no dynamic allocation allowed) ---------
__device__ int8_t g_ahi[(size_t)NROWS * DDIM];   // 16 MB
__device__ int8_t g_alo[(size_t)NROWS * DDIM];   // 16 MB
__device__ int8_t g_bhi[NSPK * DDIM];            // 256 KB
__device__ int8_t g_blo[NSPK * DDIM];            // 256 KB
__device__ float  g_psum[4 * NSPK * DDIM];       // 4 MB (4 partials/speaker)
__device__ float  g_q[NROWS];
__device__ float  g_L[NSPK];
__device__ float  g_L2[NSPK];

#define SCALE_A 4096.0f
#define SCALE_B 131072.0f
#define INV_AB  1.8626451492309570e-9f   // 1/(SCALE_A*SCALE_B) = 2^-29

// ---------------- helpers -------------------------------------------------
static __device__ __forceinline__ uint32_t smem_u32(const void* p) {
    uint32_t a;
    asm("{ .reg .u64 t; cvta.to.shared.u64 t, %1; cvt.u32.u64 %0, t; }" : "=r"(a) : "l"(p));
    return a;
}
static __device__ __forceinline__ void cp16(uint32_t d, const void* s) {
    asm volatile("cp.async.cg.shared.global [%0], [%1], 16;\n" :: "r"(d), "l"(s));
}
static __device__ __forceinline__ void cp_commit() {
    asm volatile("cp.async.commit_group;\n" ::: "memory");
}
template <int N> static __device__ __forceinline__ void cp_wait() {
    asm volatile("cp.async.wait_group %0;\n" :: "n"(N) : "memory");
}
static __device__ __forceinline__ void ldsm4(uint32_t* r, uint32_t addr) {
    asm volatile("ldmatrix.sync.aligned.m8n8.x4.shared.b16 {%0,%1,%2,%3}, [%4];"
                 : "=r"(r[0]), "=r"(r[1]), "=r"(r[2]), "=r"(r[3]) : "r"(addr));
}
// int8 MMA: m16n8k32, s32 accumulators (exact integer arithmetic)
static __device__ __forceinline__ void mma_s8(int* d, const uint32_t* a, const uint32_t* b) {
    asm volatile("mma.sync.aligned.m16n8k32.row.col.s32.s8.s8.s32 "
                 "{%0,%1,%2,%3}, {%4,%5,%6,%7}, {%8,%9}, {%0,%1,%2,%3};"
                 : "+r"(d[0]), "+r"(d[1]), "+r"(d[2]), "+r"(d[3])
                 : "r"(a[0]), "r"(a[1]), "r"(a[2]), "r"(a[3]), "r"(b[0]), "r"(b[1]));
}

// quantize x -> 16-bit fixed point, split to two int8 digits (base 256)
static __device__ __forceinline__ void quant16(float x, float scale, int& hi, int& lo) {
    int v = __float2int_rn(x * scale);
    v = max(-32639, min(32639, v));
    hi = (v + 128) >> 8;
    lo = v - (hi << 8);
}

// ======================= K1: stats + int8 split ===========================
// 1024 blocks: 4 per speaker, 16 rows each. 256 threads (thread = 4 columns).
__global__ void __launch_bounds__(256) k1_stats_split(const float* __restrict__ in) {
    int bid = blockIdx.x;
    int spk = bid >> 2, part = bid & 3;
    int tid = threadIdx.x, w = tid >> 5, l = tid & 31;
    __shared__ float qp[16][8];

    float c0 = 0.f, c1 = 0.f, c2 = 0.f, c3 = 0.f;
    size_t rowbase = ((size_t)spk * MUTT + part * 16) * DDIM;
    const float4* src = (const float4*)(in + rowbase);

    #pragma unroll 4
    for (int r = 0; r < 16; r++) {
        float4 v = src[r * (DDIM / 4) + tid];
        c0 += v.x; c1 += v.y; c2 += v.z; c3 += v.w;
        float q = v.x * v.x + v.y * v.y + v.z * v.z + v.w * v.w;
        #pragma unroll
        for (int o = 16; o; o >>= 1) q += __shfl_down_sync(0xffffffffu, q, o);
        if (l == 0) qp[r][w] = q;

        int hx, lx, hy, ly, hz, lz, hw2, lw2;
        quant16(v.x, SCALE_A, hx, lx);
        quant16(v.y, SCALE_A, hy, ly);
        quant16(v.z, SCALE_A, hz, lz);
        quant16(v.w, SCALE_A, hw2, lw2);
        uint32_t ph = (uint32_t)(hx & 0xff) | ((uint32_t)(hy & 0xff) << 8) |
                      ((uint32_t)(hz & 0xff) << 16) | ((uint32_t)(hw2 & 0xff) << 24);
        uint32_t pl = (uint32_t)(lx & 0xff) | ((uint32_t)(ly & 0xff) << 8) |
                      ((uint32_t)(lz & 0xff) << 16) | ((uint32_t)(lw2 & 0xff) << 24);
        size_t eoff = rowbase + (size_t)r * DDIM + (size_t)tid * 4;
        *(uint32_t*)(g_ahi + eoff) = ph;
        *(uint32_t*)(g_alo + eoff) = pl;
    }
    __syncthreads();
    if (tid < 16) {
        float s = 0.f;
        #pragma unroll
        for (int i = 0; i < 8; i++) s += qp[tid][i];
        g_q[spk * MUTT + part * 16 + tid] = s;
    }
    float4 s4; s4.x = c0; s4.y = c1; s4.z = c2; s4.w = c3;
    ((float4*)g_psum)[(size_t)bid * (DDIM / 4) + tid] = s4;
}

// ======================= K2: centers ======================================
__global__ void __launch_bounds__(256) k2_center() {
    int spk = blockIdx.x, tid = threadIdx.x;
    int w = tid >> 5, l = tid & 31;
    __shared__ float wp[8];
    float4 s4 = make_float4(0.f, 0.f, 0.f, 0.f);
    #pragma unroll
    for (int p = 0; p < 4; p++) {
        float4 t = ((const float4*)g_psum)[(size_t)(spk * 4 + p) * (DDIM / 4) + tid];
        s4.x += t.x; s4.y += t.y; s4.z += t.z; s4.w += t.w;
    }
    float4 m;
    m.x = s4.x * 0.015625f; m.y = s4.y * 0.015625f;
    m.z = s4.z * 0.015625f; m.w = s4.w * 0.015625f;
    float p = m.x * m.x + m.y * m.y + m.z * m.z + m.w * m.w;
    #pragma unroll
    for (int o = 16; o; o >>= 1) p += __shfl_down_sync(0xffffffffu, p, o);
    if (l == 0) wp[w] = p;
    __syncthreads();
    float ms = 0.f;
    #pragma unroll
    for (int i = 0; i < 8; i++) ms += wp[i];
    float r = 1.f / sqrtf(fmaxf(ms, 1e-12f));
    float cx = m.x * r, cy = m.y * r, cz = m.z * r, cw = m.w * r;

    int hx, lx, hy, ly, hz, lz, hw2, lw2;
    quant16(cx, SCALE_B, hx, lx);
    quant16(cy, SCALE_B, hy, ly);
    quant16(cz, SCALE_B, hz, lz);
    quant16(cw, SCALE_B, hw2, lw2);
    uint32_t ph = (uint32_t)(hx & 0xff) | ((uint32_t)(hy & 0xff) << 8) |
                  ((uint32_t)(hz & 0xff) << 16) | ((uint32_t)(hw2 & 0xff) << 24);
    uint32_t pl = (uint32_t)(lx & 0xff) | ((uint32_t)(ly & 0xff) << 8) |
                  ((uint32_t)(lz & 0xff) << 16) | ((uint32_t)(lw2 & 0xff) << 24);
    size_t off = (size_t)spk * DDIM + (size_t)tid * 4;
    *(uint32_t*)(g_bhi + off) = ph;
    *(uint32_t*)(g_blo + off) = pl;

    if (tid == 0) {
        g_L[spk]  = 64.f * sqrtf(ms);
        g_L2[spk] = 4096.f * ms;
    }
}

// ======================= K3: int8 MMA GEMM + fused epilogue ===============
// CTA tile 128(M) x 64(N), BK=64 int8. 8 warps: 4(M) x 2(N), warp 32x32.
// 3 int32 accumulator sets: hh, m(=hl+lh), ll. dot = (hh*2^16 + m*2^8 + ll)/2^29.
#define ROWB 80
#define A_HI 0
#define A_LO 10240
#define B_HI 20480
#define B_LO 25600
#define ST_STRIDE 30720
#define K3_SMEM (2 * ST_STRIDE)

static __device__ __forceinline__ void k3_loads(uint32_t sm, int s, int kst, int tid,
                                                int ctaM, int ctaN) {
    uint32_t sb = sm + (uint32_t)s * ST_STRIDE;
    const char* ahi = (const char*)g_ahi;
    const char* alo = (const char*)g_alo;
    const char* bhi = (const char*)g_bhi;
    const char* blo = (const char*)g_blo;
    size_t kb = (size_t)kst * 64;   // byte offset in 1024-byte row
    // A: 128 rows x 64B per digit -> 512 chunks, 2 per thread per digit
    #pragma unroll
    for (int i = 0; i < 2; i++) {
        int c = tid + i * 256;
        int row = c >> 2; uint32_t sub = (uint32_t)(c & 3) * 16u;
        size_t go = ((size_t)(ctaM * 128 + row)) * DDIM + kb + sub;
        cp16(sb + A_HI + (uint32_t)row * ROWB + sub, ahi + go);
        cp16(sb + A_LO + (uint32_t)row * ROWB + sub, alo + go);
    }
    // B: 64 rows x 64B per digit -> 256 chunks, 1 per thread per digit
    {
        int row = tid >> 2; uint32_t sub = (uint32_t)(tid & 3) * 16u;
        size_t go = ((size_t)(ctaN * 64 + row)) * DDIM + kb + sub;
        cp16(sb + B_HI + (uint32_t)row * ROWB + sub, bhi + go);
        cp16(sb + B_LO + (uint32_t)row * ROWB + sub, blo + go);
    }
}

__global__ void __launch_bounds__(256, 1) k3_gemm(const float* __restrict__ w_p,
                                                  const float* __restrict__ b_p,
                                                  float* __restrict__ out) {
    extern __shared__ char smem[];
    uint32_t sm = smem_u32(smem);
    int tid = threadIdx.x, wid = tid >> 5, lane = tid & 31;
    int ctaN = blockIdx.x & 3, ctaM = blockIdx.x >> 2;
    int warpM = wid >> 1, warpN = wid & 1;

    // per-lane ldmatrix base offsets (within stage, bytes)
    uint32_t aoff[2], boff[2];
    {
        uint32_t ars = (uint32_t)(lane & 15);
        uint32_t acs = (uint32_t)(lane >> 4) * 16u;
        uint32_t brs = (uint32_t)((lane & 7) + ((lane >> 4) << 3));
        uint32_t bcs = (uint32_t)((lane >> 3) & 1) * 16u;
        #pragma unroll
        for (int mt = 0; mt < 2; mt++)
            aoff[mt] = (uint32_t)(warpM * 32 + mt * 16 + ars) * ROWB + acs;
        #pragma unroll
        for (int np = 0; np < 2; np++)
            boff[np] = (uint32_t)(warpN * 32 + np * 16 + brs) * ROWB + bcs;
    }

    int ahh[2][4][4], amm[2][4][4], all_[2][4][4];
    #pragma unroll
    for (int mt = 0; mt < 2; mt++)
        #pragma unroll
        for (int nt = 0; nt < 4; nt++)
            #pragma unroll
            for (int e = 0; e < 4; e++) { ahh[mt][nt][e] = 0; amm[mt][nt][e] = 0; all_[mt][nt][e] = 0; }

    k3_loads(sm, 0, 0, tid, ctaM, ctaN); cp_commit();
    k3_loads(sm, 1, 1, tid, ctaM, ctaN); cp_commit();

    #pragma unroll 1
    for (int k = 0; k < 16; k++) {
        int s = k & 1;
        if (k < 15) cp_wait<1>(); else cp_wait<0>();
        __syncthreads();
        uint32_t sb = sm + (uint32_t)s * ST_STRIDE;

        #pragma unroll
        for (int ks = 0; ks < 2; ks++) {
            uint32_t kb = (uint32_t)ks * 32u;
            uint32_t ah[2][4], al[2][4], bh[4][2], bl[4][2];
            #pragma unroll
            for (int mt = 0; mt < 2; mt++) {
                ldsm4(ah[mt], sb + A_HI + aoff[mt] + kb);
                ldsm4(al[mt], sb + A_LO + aoff[mt] + kb);
            }
            #pragma unroll
            for (int np = 0; np < 2; np++) {
                uint32_t t[4];
                ldsm4(t, sb + B_HI + boff[np] + kb);
                bh[2 * np][0] = t[0]; bh[2 * np][1] = t[1];
                bh[2 * np + 1][0] = t[2]; bh[2 * np + 1][1] = t[3];
                ldsm4(t, sb + B_LO + boff[np] + kb);
                bl[2 * np][0] = t[0]; bl[2 * np][1] = t[1];
                bl[2 * np + 1][0] = t[2]; bl[2 * np + 1][1] = t[3];
            }
            #pragma unroll
            for (int mt = 0; mt < 2; mt++)
                #pragma unroll
                for (int nt = 0; nt < 4; nt++) {
                    mma_s8(ahh[mt][nt], ah[mt], bh[nt]);
                    mma_s8(amm[mt][nt], ah[mt], bl[nt]);
                    mma_s8(amm[mt][nt], al[mt], bh[nt]);
                    mma_s8(all_[mt][nt], al[mt], bl[nt]);
                }
        }

        if (k + 2 < 16) {
            __syncthreads();
            k3_loads(sm, s, k + 2, tid, ctaM, ctaN);
            cp_commit();
        }
    }

    // ---- fused epilogue ----
    float W = w_p[0], Bb = b_p[0];
    #pragma unroll
    for (int mt = 0; mt < 2; mt++) {
        int r0 = ctaM * 128 + warpM * 32 + mt * 16 + (lane >> 2);
        int r1 = r0 + 8;
        int j0 = r0 >> 6, j1 = r1 >> 6;
        float q0 = g_q[r0], q1 = g_q[r1];
        float La = g_L[j0], L2a = g_L2[j0];
        float Lb = g_L[j1], L2b = g_L2[j1];
        #pragma unroll
        for (int nt = 0; nt < 4; nt++) {
            int c = ctaN * 64 + warpN * 32 + nt * 8 + (lane & 3) * 2;
            float v[4];
            #pragma unroll
            for (int e = 0; e < 4; e++)
                v[e] = ((float)ahh[mt][nt][e] * 65536.f +
                        (float)amm[mt][nt][e] * 256.f +
                        (float)all_[mt][nt][e]) * INV_AB;
            if (c == j0 || c + 1 == j0) {
                float g = (c == j0) ? v[0] : v[1];
                float sv = g * La;
                float dg = (sv - q0) / sqrtf(fmaxf(L2a - 2.f * sv + q0, 1e-12f));
                if (c == j0) v[0] = dg; else v[1] = dg;
            }
            if (c == j1 || c + 1 == j1) {
                float g = (c == j1) ? v[2] : v[3];
                float sv = g * Lb;
                float dg = (sv - q1) / sqrtf(fmaxf(L2b - 2.f * sv + q1, 1e-12f));
                if (c == j1) v[2] = dg; else v[3] = dg;
            }
            float2 o0, o1;
            o0.x = W * v[0] + Bb; o0.y = W * v[1] + Bb;
            o1.x = W * v[2] + Bb; o1.y = W * v[3] + Bb;
            *(float2*)(out + (size_t)r0 * 256 + c) = o0;
            *(float2*)(out + (size_t)r1 * 256 + c) = o1;
        }
    }
}

// ======================= launch ===========================================
extern "C" void kernel_launch(void* const* d_in, const int* in_sizes, int n_in,
                              void* d_out, int out_size) {
    const float* in = (const float*)d_in[0];
    const float* w  = (const float*)d_in[1];
    const float* b  = (const float*)d_in[2];
    float* out = (float*)d_out;
    (void)in_sizes; (void)n_in; (void)out_size;

    cudaFuncSetAttribute(k3_gemm, cudaFuncAttributeMaxDynamicSharedMemorySize, K3_SMEM);

    k1_stats_split<<<NSPK * 4, 256>>>(in);
    k2_center<<<NSPK, 256>>>();
    k3_gemm<<<(NROWS / 128) * 4, 256, K3_SMEM>>>(w, b, out);
}

// round 5
// speedup vs baseline: 3.6748x; 3.6748x over previous
#include <cuda_runtime.h>
#include <cuda_fp16.h>
#include <stdint.h>

#define NSPK 256
#define MUTT 64
#define DDIM 1024
#define NROWS (NSPK*MUTT)   // 16384

// ---------------- device scratch (no dynamic allocation allowed) ---------
__device__ __half g_a[(size_t)NROWS * DDIM];     // 32 MB  (A, single fp16 plane)
__device__ __half g_bh[NSPK * DDIM];             // 512 KB (B hi)
__device__ __half g_bl[NSPK * DDIM];             // 512 KB (B lo)
__device__ float  g_psum[8 * NSPK * DDIM];       // 8 MB (8 partials/speaker)
__device__ float  g_q[NROWS];
__device__ float  g_L[NSPK];
__device__ float  g_L2[NSPK];

// ---------------- helpers -------------------------------------------------
static __device__ __forceinline__ uint32_t smem_u32(const void* p) {
    uint32_t a;
    asm("{ .reg .u64 t; cvta.to.shared.u64 t, %1; cvt.u32.u64 %0, t; }" : "=r"(a) : "l"(p));
    return a;
}
static __device__ __forceinline__ void cp16(uint32_t d, const void* s) {
    asm volatile("cp.async.cg.shared.global [%0], [%1], 16;\n" :: "r"(d), "l"(s));
}
static __device__ __forceinline__ void cp_commit() {
    asm volatile("cp.async.commit_group;\n" ::: "memory");
}
template <int N> static __device__ __forceinline__ void cp_wait() {
    asm volatile("cp.async.wait_group %0;\n" :: "n"(N) : "memory");
}
static __device__ __forceinline__ void ldsm4(uint32_t* r, uint32_t addr) {
    asm volatile("ldmatrix.sync.aligned.m8n8.x4.shared.b16 {%0,%1,%2,%3}, [%4];"
                 : "=r"(r[0]), "=r"(r[1]), "=r"(r[2]), "=r"(r[3]) : "r"(addr));
}
static __device__ __forceinline__ void mma_f16(float* d, const uint32_t* a, const uint32_t* b) {
    asm volatile("mma.sync.aligned.m16n8k16.row.col.f32.f16.f16.f32 "
                 "{%0,%1,%2,%3}, {%4,%5,%6,%7}, {%8,%9}, {%0,%1,%2,%3};"
                 : "+f"(d[0]), "+f"(d[1]), "+f"(d[2]), "+f"(d[3])
                 : "r"(a[0]), "r"(a[1]), "r"(a[2]), "r"(a[3]), "r"(b[0]), "r"(b[1]));
}

// ======================= K1: stats + fp16 A plane =========================
// 2048 blocks: 8 per speaker, 8 rows each. 256 threads (thread = 4 columns).
__global__ void __launch_bounds__(256) k1_stats(const float* __restrict__ in) {
    int bid = blockIdx.x;
    int spk = bid >> 3, part = bid & 7;
    int tid = threadIdx.x, w = tid >> 5, l = tid & 31;
    __shared__ float qp[8][8];

    float c0 = 0.f, c1 = 0.f, c2 = 0.f, c3 = 0.f;
    size_t rowbase = ((size_t)spk * MUTT + part * 8) * DDIM;
    const float4* src = (const float4*)(in + rowbase);

    #pragma unroll
    for (int r = 0; r < 8; r++) {
        float4 v = src[r * (DDIM / 4) + tid];
        c0 += v.x; c1 += v.y; c2 += v.z; c3 += v.w;
        float q = v.x * v.x + v.y * v.y + v.z * v.z + v.w * v.w;
        #pragma unroll
        for (int o = 16; o; o >>= 1) q += __shfl_down_sync(0xffffffffu, q, o);
        if (l == 0) qp[r][w] = q;

        union { __half2 h2[2]; uint2 u; } ph;
        ph.h2[0] = __floats2half2_rn(v.x, v.y);
        ph.h2[1] = __floats2half2_rn(v.z, v.w);
        *(uint2*)(g_a + rowbase + (size_t)r * DDIM + (size_t)tid * 4) = ph.u;
    }
    __syncthreads();
    if (tid < 8) {
        float s = 0.f;
        #pragma unroll
        for (int i = 0; i < 8; i++) s += qp[tid][i];
        g_q[spk * MUTT + part * 8 + tid] = s;
    }
    float4 s4; s4.x = c0; s4.y = c1; s4.z = c2; s4.w = c3;
    ((float4*)g_psum)[(size_t)bid * (DDIM / 4) + tid] = s4;
}

// ======================= K2: centers (fp16 hi/lo split) ===================
__global__ void __launch_bounds__(256) k2_center() {
    int spk = blockIdx.x, tid = threadIdx.x;
    int w = tid >> 5, l = tid & 31;
    __shared__ float wp[8];
    float4 s4 = make_float4(0.f, 0.f, 0.f, 0.f);
    #pragma unroll
    for (int p = 0; p < 8; p++) {
        float4 t = ((const float4*)g_psum)[(size_t)(spk * 8 + p) * (DDIM / 4) + tid];
        s4.x += t.x; s4.y += t.y; s4.z += t.z; s4.w += t.w;
    }
    float4 m;
    m.x = s4.x * 0.015625f; m.y = s4.y * 0.015625f;
    m.z = s4.z * 0.015625f; m.w = s4.w * 0.015625f;
    float p = m.x * m.x + m.y * m.y + m.z * m.z + m.w * m.w;
    #pragma unroll
    for (int o = 16; o; o >>= 1) p += __shfl_down_sync(0xffffffffu, p, o);
    if (l == 0) wp[w] = p;
    __syncthreads();
    float ms = 0.f;
    #pragma unroll
    for (int i = 0; i < 8; i++) ms += wp[i];
    float r = 1.f / sqrtf(fmaxf(ms, 1e-12f));
    float c[4] = { m.x * r, m.y * r, m.z * r, m.w * r };

    __half hi[4]; float lo[4];
    #pragma unroll
    for (int i = 0; i < 4; i++) {
        hi[i] = __float2half_rn(c[i]);
        lo[i] = c[i] - __half2float(hi[i]);
    }
    union { __half2 h2[2]; uint2 u; } ph, pl;
    ph.h2[0] = __halves2half2(hi[0], hi[1]); ph.h2[1] = __halves2half2(hi[2], hi[3]);
    pl.h2[0] = __floats2half2_rn(lo[0], lo[1]); pl.h2[1] = __floats2half2_rn(lo[2], lo[3]);
    size_t off = (size_t)spk * DDIM + (size_t)tid * 4;
    *(uint2*)(g_bh + off) = ph.u;
    *(uint2*)(g_bl + off) = pl.u;

    if (tid == 0) {
        g_L[spk]  = 64.f * sqrtf(ms);
        g_L2[spk] = 4096.f * ms;
    }
}

// ======================= K3: fp16 HMMA GEMM + fused epilogue ==============
// CTA tile 128(M) x 256(N), BK=32 fp16. 8 warps: 2(M) x 4(N), warp 64x64.
// acc += A*Bhi + A*Blo  (single fp32 accumulator; B split kills B quant error)
// smem rows padded to 80B; 3 stages, one __syncthreads per k-iter.
#define ROWB 80
#define A_OFF 0
#define B_HI 10240
#define B_LO 30720
#define ST_STRIDE 51200
#define K3_SMEM (3 * ST_STRIDE)

static __device__ __forceinline__ void k3_loads(uint32_t sm, int st, int kst, int tid, int ctaM) {
    uint32_t sb = sm + (uint32_t)st * ST_STRIDE;
    const char* ap = (const char*)g_a;
    const char* bhp = (const char*)g_bh;
    const char* blp = (const char*)g_bl;
    size_t kb = (size_t)kst * 64;   // byte offset within 2048-byte row
    // A: 128 rows x 64B -> 512 chunks, 2/thread
    #pragma unroll
    for (int i = 0; i < 2; i++) {
        int c = tid + i * 256;
        int row = c >> 2; uint32_t sub = (uint32_t)(c & 3) * 16u;
        size_t go = ((size_t)(ctaM * 128 + row)) * 2048 + kb + sub;
        cp16(sb + A_OFF + (uint32_t)row * ROWB + sub, ap + go);
    }
    // B: 256 rows x 64B per plane -> 1024 chunks/plane, 4/thread/plane
    #pragma unroll
    for (int i = 0; i < 4; i++) {
        int c = tid + i * 256;
        int row = c >> 2; uint32_t sub = (uint32_t)(c & 3) * 16u;
        size_t go = (size_t)row * 2048 + kb + sub;
        cp16(sb + B_HI + (uint32_t)row * ROWB + sub, bhp + go);
        cp16(sb + B_LO + (uint32_t)row * ROWB + sub, blp + go);
    }
}

__global__ void __launch_bounds__(256, 1) k3_gemm(const float* __restrict__ w_p,
                                                  const float* __restrict__ b_p,
                                                  float* __restrict__ out) {
    extern __shared__ char smem[];
    uint32_t sm = smem_u32(smem);
    int tid = threadIdx.x, wid = tid >> 5, lane = tid & 31, ctaM = blockIdx.x;
    int warpM = wid >> 2, warpN = wid & 3;

    uint32_t aoff[4], boff[4];
    {
        uint32_t ars = (uint32_t)(lane & 15);
        uint32_t acs = (uint32_t)(lane >> 4) * 16u;
        uint32_t brs = (uint32_t)((lane & 7) + ((lane >> 4) << 3));
        uint32_t bcs = (uint32_t)((lane >> 3) & 1) * 16u;
        #pragma unroll
        for (int mt = 0; mt < 4; mt++)
            aoff[mt] = (uint32_t)(warpM * 64 + mt * 16 + ars) * ROWB + acs;
        #pragma unroll
        for (int np = 0; np < 4; np++)
            boff[np] = (uint32_t)(warpN * 64 + np * 16 + brs) * ROWB + bcs;
    }

    float acc[4][8][4];
    #pragma unroll
    for (int mt = 0; mt < 4; mt++)
        #pragma unroll
        for (int nt = 0; nt < 8; nt++)
            #pragma unroll
            for (int i = 0; i < 4; i++) acc[mt][nt][i] = 0.f;

    k3_loads(sm, 0, 0, tid, ctaM); cp_commit();
    k3_loads(sm, 1, 1, tid, ctaM); cp_commit();

    #pragma unroll 1
    for (int k = 0; k < 32; k++) {
        int s = k - (k / 3) * 3;      // k % 3
        if (k < 31) cp_wait<1>(); else cp_wait<0>();
        __syncthreads();
        // prefetch k+2 into stage (k+2)%3 (safe: all warps past sync of iter k)
        if (k + 2 < 32) {
            int s2 = (k + 2) - ((k + 2) / 3) * 3;
            k3_loads(sm, s2, k + 2, tid, ctaM);
            cp_commit();
        }
        uint32_t sb = sm + (uint32_t)s * ST_STRIDE;

        #pragma unroll
        for (int ks = 0; ks < 2; ks++) {
            uint32_t kb = (uint32_t)ks * 32u;
            uint32_t a[4][4], bh[8][2], bl[8][2];
            #pragma unroll
            for (int mt = 0; mt < 4; mt++)
                ldsm4(a[mt], sb + A_OFF + aoff[mt] + kb);
            #pragma unroll
            for (int np = 0; np < 4; np++) {
                uint32_t t[4];
                ldsm4(t, sb + B_HI + boff[np] + kb);
                bh[2 * np][0] = t[0]; bh[2 * np][1] = t[1];
                bh[2 * np + 1][0] = t[2]; bh[2 * np + 1][1] = t[3];
                ldsm4(t, sb + B_LO + boff[np] + kb);
                bl[2 * np][0] = t[0]; bl[2 * np][1] = t[1];
                bl[2 * np + 1][0] = t[2]; bl[2 * np + 1][1] = t[3];
            }
            #pragma unroll
            for (int mt = 0; mt < 4; mt++)
                #pragma unroll
                for (int nt = 0; nt < 8; nt++) {
                    mma_f16(acc[mt][nt], a[mt], bh[nt]);
                    mma_f16(acc[mt][nt], a[mt], bl[nt]);
                }
        }
    }

    // ---- fused epilogue ----
    float W = w_p[0], Bb = b_p[0];
    #pragma unroll
    for (int mt = 0; mt < 4; mt++) {
        int r0 = ctaM * 128 + warpM * 64 + mt * 16 + (lane >> 2);
        int r1 = r0 + 8;
        int j0 = r0 >> 6, j1 = r1 >> 6;
        float q0 = g_q[r0], q1 = g_q[r1];
        float La = g_L[j0], L2a = g_L2[j0];
        float Lb = g_L[j1], L2b = g_L2[j1];
        #pragma unroll
        for (int nt = 0; nt < 8; nt++) {
            int c = warpN * 64 + nt * 8 + (lane & 3) * 2;
            float v0 = acc[mt][nt][0], v1 = acc[mt][nt][1];
            float v2 = acc[mt][nt][2], v3 = acc[mt][nt][3];
            if (c == j0 || c + 1 == j0) {
                float g = (c == j0) ? v0 : v1;
                float sv = g * La;
                float dg = (sv - q0) / sqrtf(fmaxf(L2a - 2.f * sv + q0, 1e-12f));
                if (c == j0) v0 = dg; else v1 = dg;
            }
            if (c == j1 || c + 1 == j1) {
                float g = (c == j1) ? v2 : v3;
                float sv = g * Lb;
                float dg = (sv - q1) / sqrtf(fmaxf(L2b - 2.f * sv + q1, 1e-12f));
                if (c == j1) v2 = dg; else v3 = dg;
            }
            float2 o0, o1;
            o0.x = W * v0 + Bb; o0.y = W * v1 + Bb;
            o1.x = W * v2 + Bb; o1.y = W * v3 + Bb;
            *(float2*)(out + (size_t)r0 * 256 + c) = o0;
            *(float2*)(out + (size_t)r1 * 256 + c) = o1;
        }
    }
}

// ======================= launch ===========================================
extern "C" void kernel_launch(void* const* d_in, const int* in_sizes, int n_in,
                              void* d_out, int out_size) {
    const float* in = (const float*)d_in[0];
    const float* w  = (const float*)d_in[1];
    const float* b  = (const float*)d_in[2];
    float* out = (float*)d_out;
    (void)in_sizes; (void)n_in; (void)out_size;

    cudaFuncSetAttribute(k3_gemm, cudaFuncAttributeMaxDynamicSharedMemorySize, K3_SMEM);

    k1_stats<<<NSPK * 8, 256>>>(in);
    k2_center<<<NSPK, 256>>>();
    k3_gemm<<<NROWS / 128, 256, K3_SMEM>>>(w, b, out);
}

// round 6
// speedup vs baseline: 5.1733x; 1.4078x over previous
#include <cuda_runtime.h>
#include <cuda_fp16.h>
#include <stdint.h>

#define NSPK 256
#define MUTT 64
#define DDIM 1024
#define NROWS (NSPK*MUTT)   // 16384

// ---------------- device scratch (no dynamic allocation allowed) ---------
__device__ __half g_a[(size_t)NROWS * DDIM];     // 32 MB  (A, fp16)
__device__ __half g_b[NSPK * DDIM];              // 512 KB (B, fp16)
__device__ float  g_psum[8 * NSPK * DDIM];       // 8 MB (8 partials/speaker)
__device__ float  g_q[NROWS];
__device__ float  g_L[NSPK];
__device__ float  g_L2[NSPK];

// ---------------- helpers -------------------------------------------------
static __device__ __forceinline__ uint32_t smem_u32(const void* p) {
    uint32_t a;
    asm("{ .reg .u64 t; cvta.to.shared.u64 t, %1; cvt.u32.u64 %0, t; }" : "=r"(a) : "l"(p));
    return a;
}
static __device__ __forceinline__ void cp16(uint32_t d, const void* s) {
    asm volatile("cp.async.cg.shared.global [%0], [%1], 16;\n" :: "r"(d), "l"(s));
}
static __device__ __forceinline__ void cp_commit() {
    asm volatile("cp.async.commit_group;\n" ::: "memory");
}
template <int N> static __device__ __forceinline__ void cp_wait() {
    asm volatile("cp.async.wait_group %0;\n" :: "n"(N) : "memory");
}
static __device__ __forceinline__ void ldsm4(uint32_t* r, uint32_t addr) {
    asm volatile("ldmatrix.sync.aligned.m8n8.x4.shared.b16 {%0,%1,%2,%3}, [%4];"
                 : "=r"(r[0]), "=r"(r[1]), "=r"(r[2]), "=r"(r[3]) : "r"(addr));
}
static __device__ __forceinline__ void mma_f16(float* d, const uint32_t* a, const uint32_t* b) {
    asm volatile("mma.sync.aligned.m16n8k16.row.col.f32.f16.f16.f32 "
                 "{%0,%1,%2,%3}, {%4,%5,%6,%7}, {%8,%9}, {%0,%1,%2,%3};"
                 : "+f"(d[0]), "+f"(d[1]), "+f"(d[2]), "+f"(d[3])
                 : "r"(a[0]), "r"(a[1]), "r"(a[2]), "r"(a[3]), "r"(b[0]), "r"(b[1]));
}

// ======================= K1: stats + fp16 A plane =========================
// 2048 blocks: 8 per speaker, 8 rows each. 256 threads (thread = 4 columns).
__global__ void __launch_bounds__(256) k1_stats(const float* __restrict__ in) {
    int bid = blockIdx.x;
    int spk = bid >> 3, part = bid & 7;
    int tid = threadIdx.x, w = tid >> 5, l = tid & 31;
    __shared__ float qp[8][8];

    float c0 = 0.f, c1 = 0.f, c2 = 0.f, c3 = 0.f;
    size_t rowbase = ((size_t)spk * MUTT + part * 8) * DDIM;
    const float4* src = (const float4*)(in + rowbase);

    #pragma unroll
    for (int r = 0; r < 8; r++) {
        float4 v = src[r * (DDIM / 4) + tid];
        c0 += v.x; c1 += v.y; c2 += v.z; c3 += v.w;
        float q = v.x * v.x + v.y * v.y + v.z * v.z + v.w * v.w;
        #pragma unroll
        for (int o = 16; o; o >>= 1) q += __shfl_down_sync(0xffffffffu, q, o);
        if (l == 0) qp[r][w] = q;

        union { __half2 h2[2]; uint2 u; } ph;
        ph.h2[0] = __floats2half2_rn(v.x, v.y);
        ph.h2[1] = __floats2half2_rn(v.z, v.w);
        *(uint2*)(g_a + rowbase + (size_t)r * DDIM + (size_t)tid * 4) = ph.u;
    }
    __syncthreads();
    if (tid < 8) {
        float s = 0.f;
        #pragma unroll
        for (int i = 0; i < 8; i++) s += qp[tid][i];
        g_q[spk * MUTT + part * 8 + tid] = s;
    }
    float4 s4; s4.x = c0; s4.y = c1; s4.z = c2; s4.w = c3;
    ((float4*)g_psum)[(size_t)bid * (DDIM / 4) + tid] = s4;
}

// ======================= K2: centers (fp16) ===============================
__global__ void __launch_bounds__(256) k2_center() {
    int spk = blockIdx.x, tid = threadIdx.x;
    int w = tid >> 5, l = tid & 31;
    __shared__ float wp[8];
    float4 s4 = make_float4(0.f, 0.f, 0.f, 0.f);
    #pragma unroll
    for (int p = 0; p < 8; p++) {
        float4 t = ((const float4*)g_psum)[(size_t)(spk * 8 + p) * (DDIM / 4) + tid];
        s4.x += t.x; s4.y += t.y; s4.z += t.z; s4.w += t.w;
    }
    float4 m;
    m.x = s4.x * 0.015625f; m.y = s4.y * 0.015625f;
    m.z = s4.z * 0.015625f; m.w = s4.w * 0.015625f;
    float p = m.x * m.x + m.y * m.y + m.z * m.z + m.w * m.w;
    #pragma unroll
    for (int o = 16; o; o >>= 1) p += __shfl_down_sync(0xffffffffu, p, o);
    if (l == 0) wp[w] = p;
    __syncthreads();
    float ms = 0.f;
    #pragma unroll
    for (int i = 0; i < 8; i++) ms += wp[i];
    float r = 1.f / sqrtf(fmaxf(ms, 1e-12f));

    union { __half2 h2[2]; uint2 u; } ph;
    ph.h2[0] = __floats2half2_rn(m.x * r, m.y * r);
    ph.h2[1] = __floats2half2_rn(m.z * r, m.w * r);
    *(uint2*)(g_b + (size_t)spk * DDIM + (size_t)tid * 4) = ph.u;

    if (tid == 0) {
        g_L[spk]  = 64.f * sqrtf(ms);
        g_L2[spk] = 4096.f * ms;
    }
}

// ======================= K3: fp16 HMMA GEMM + fused epilogue ==============
// CTA tile 128(M) x 256(N), BK=32 fp16. 8 warps: 2(M) x 4(N), warp 64x64.
// Single fp16 MMA per tile. smem rows padded to 80B; 4-stage ring, prefetch d=3.
#define ROWB 80
#define A_OFF 0
#define B_OFF 10240
#define ST_STRIDE 30720
#define K3_SMEM (4 * ST_STRIDE)

static __device__ __forceinline__ void k3_loads(uint32_t sm, int st, int kst, int tid, int ctaM) {
    uint32_t sb = sm + (uint32_t)st * ST_STRIDE;
    const char* ap = (const char*)g_a;
    const char* bp = (const char*)g_b;
    size_t kb = (size_t)kst * 64;   // byte offset within 2048-byte row
    // A: 128 rows x 64B -> 512 chunks, 2/thread
    #pragma unroll
    for (int i = 0; i < 2; i++) {
        int c = tid + i * 256;
        int row = c >> 2; uint32_t sub = (uint32_t)(c & 3) * 16u;
        size_t go = ((size_t)(ctaM * 128 + row)) * 2048 + kb + sub;
        cp16(sb + A_OFF + (uint32_t)row * ROWB + sub, ap + go);
    }
    // B: 256 rows x 64B -> 1024 chunks, 4/thread
    #pragma unroll
    for (int i = 0; i < 4; i++) {
        int c = tid + i * 256;
        int row = c >> 2; uint32_t sub = (uint32_t)(c & 3) * 16u;
        size_t go = (size_t)row * 2048 + kb + sub;
        cp16(sb + B_OFF + (uint32_t)row * ROWB + sub, bp + go);
    }
}

__global__ void __launch_bounds__(256, 1) k3_gemm(const float* __restrict__ w_p,
                                                  const float* __restrict__ b_p,
                                                  float* __restrict__ out) {
    extern __shared__ char smem[];
    uint32_t sm = smem_u32(smem);
    int tid = threadIdx.x, wid = tid >> 5, lane = tid & 31, ctaM = blockIdx.x;
    int warpM = wid >> 2, warpN = wid & 3;

    uint32_t aoff[4], boff[4];
    {
        uint32_t ars = (uint32_t)(lane & 15);
        uint32_t acs = (uint32_t)(lane >> 4) * 16u;
        uint32_t brs = (uint32_t)((lane & 7) + ((lane >> 4) << 3));
        uint32_t bcs = (uint32_t)((lane >> 3) & 1) * 16u;
        #pragma unroll
        for (int mt = 0; mt < 4; mt++)
            aoff[mt] = (uint32_t)(warpM * 64 + mt * 16 + ars) * ROWB + acs;
        #pragma unroll
        for (int np = 0; np < 4; np++)
            boff[np] = (uint32_t)(warpN * 64 + np * 16 + brs) * ROWB + bcs;
    }

    float acc[4][8][4];
    #pragma unroll
    for (int mt = 0; mt < 4; mt++)
        #pragma unroll
        for (int nt = 0; nt < 8; nt++)
            #pragma unroll
            for (int i = 0; i < 4; i++) acc[mt][nt][i] = 0.f;

    k3_loads(sm, 0, 0, tid, ctaM); cp_commit();
    k3_loads(sm, 1, 1, tid, ctaM); cp_commit();
    k3_loads(sm, 2, 2, tid, ctaM); cp_commit();

    #pragma unroll 1
    for (int k = 0; k < 32; k++) {
        int s = k & 3;
        // complete group k: pending = 3 while prefetching, then shrinking tail
        if (k <= 29) cp_wait<2>(); else if (k == 30) cp_wait<1>(); else cp_wait<0>();
        __syncthreads();
        // prefetch k+3 into stage (k+3)&3 = (k-1)&3 (freed by the barrier above)
        if (k + 3 < 32) {
            k3_loads(sm, (k + 3) & 3, k + 3, tid, ctaM);
            cp_commit();
        }
        uint32_t sb = sm + (uint32_t)s * ST_STRIDE;

        #pragma unroll
        for (int ks = 0; ks < 2; ks++) {
            uint32_t kb = (uint32_t)ks * 32u;
            uint32_t a[4][4], b[8][2];
            #pragma unroll
            for (int mt = 0; mt < 4; mt++)
                ldsm4(a[mt], sb + A_OFF + aoff[mt] + kb);
            #pragma unroll
            for (int np = 0; np < 4; np++) {
                uint32_t t[4];
                ldsm4(t, sb + B_OFF + boff[np] + kb);
                b[2 * np][0] = t[0]; b[2 * np][1] = t[1];
                b[2 * np + 1][0] = t[2]; b[2 * np + 1][1] = t[3];
            }
            #pragma unroll
            for (int mt = 0; mt < 4; mt++)
                #pragma unroll
                for (int nt = 0; nt < 8; nt++)
                    mma_f16(acc[mt][nt], a[mt], b[nt]);
        }
    }

    // ---- fused epilogue ----
    float W = w_p[0], Bb = b_p[0];
    #pragma unroll
    for (int mt = 0; mt < 4; mt++) {
        int r0 = ctaM * 128 + warpM * 64 + mt * 16 + (lane >> 2);
        int r1 = r0 + 8;
        int j0 = r0 >> 6, j1 = r1 >> 6;
        float q0 = g_q[r0], q1 = g_q[r1];
        float La = g_L[j0], L2a = g_L2[j0];
        float Lb = g_L[j1], L2b = g_L2[j1];
        #pragma unroll
        for (int nt = 0; nt < 8; nt++) {
            int c = warpN * 64 + nt * 8 + (lane & 3) * 2;
            float v0 = acc[mt][nt][0], v1 = acc[mt][nt][1];
            float v2 = acc[mt][nt][2], v3 = acc[mt][nt][3];
            if (c == j0 || c + 1 == j0) {
                float g = (c == j0) ? v0 : v1;
                float sv = g * La;
                float dg = (sv - q0) / sqrtf(fmaxf(L2a - 2.f * sv + q0, 1e-12f));
                if (c == j0) v0 = dg; else v1 = dg;
            }
            if (c == j1 || c + 1 == j1) {
                float g = (c == j1) ? v2 : v3;
                float sv = g * Lb;
                float dg = (sv - q1) / sqrtf(fmaxf(L2b - 2.f * sv + q1, 1e-12f));
                if (c == j1) v2 = dg; else v3 = dg;
            }
            float2 o0, o1;
            o0.x = W * v0 + Bb; o0.y = W * v1 + Bb;
            o1.x = W * v2 + Bb; o1.y = W * v3 + Bb;
            *(float2*)(out + (size_t)r0 * 256 + c) = o0;
            *(float2*)(out + (size_t)r1 * 256 + c) = o1;
        }
    }
}

// ======================= launch ===========================================
extern "C" void kernel_launch(void* const* d_in, const int* in_sizes, int n_in,
                              void* d_out, int out_size) {
    const float* in = (const float*)d_in[0];
    const float* w  = (const float*)d_in[1];
    const float* b  = (const float*)d_in[2];
    float* out = (float*)d_out;
    (void)in_sizes; (void)n_in; (void)out_size;

    cudaFuncSetAttribute(k3_gemm, cudaFuncAttributeMaxDynamicSharedMemorySize, K3_SMEM);

    k1_stats<<<NSPK * 8, 256>>>(in);
    k2_center<<<NSPK, 256>>>();
    k3_gemm<<<NROWS / 128, 256, K3_SMEM>>>(w, b, out);
}

// round 7
// speedup vs baseline: 5.5447x; 1.0718x over previous
#include <cuda_runtime.h>
#include <cuda_fp16.h>
#include <stdint.h>

#define NSPK 256
#define MUTT 64
#define DDIM 1024
#define NROWS (NSPK*MUTT)   // 16384

// ---------------- device scratch (no dynamic allocation allowed) ---------
__device__ __half g_a[(size_t)NROWS * DDIM];     // 32 MB  (A, fp16)
__device__ __half g_b[NSPK * DDIM];              // 512 KB (B, fp16)
__device__ float  g_psum[8 * NSPK * DDIM];       // 8 MB (8 partials/speaker)
__device__ float  g_q[NROWS];
__device__ float  g_L[NSPK];
__device__ float  g_L2[NSPK];

// ---------------- helpers -------------------------------------------------
static __device__ __forceinline__ uint32_t smem_u32(const void* p) {
    uint32_t a;
    asm("{ .reg .u64 t; cvta.to.shared.u64 t, %1; cvt.u32.u64 %0, t; }" : "=r"(a) : "l"(p));
    return a;
}
static __device__ __forceinline__ void cp16(uint32_t d, const void* s) {
    asm volatile("cp.async.cg.shared.global [%0], [%1], 16;\n" :: "r"(d), "l"(s));
}
static __device__ __forceinline__ void cp_commit() {
    asm volatile("cp.async.commit_group;\n" ::: "memory");
}
template <int N> static __device__ __forceinline__ void cp_wait() {
    asm volatile("cp.async.wait_group %0;\n" :: "n"(N) : "memory");
}
static __device__ __forceinline__ void ldsm4(uint32_t* r, uint32_t addr) {
    asm volatile("ldmatrix.sync.aligned.m8n8.x4.shared.b16 {%0,%1,%2,%3}, [%4];"
                 : "=r"(r[0]), "=r"(r[1]), "=r"(r[2]), "=r"(r[3]) : "r"(addr));
}
static __device__ __forceinline__ void mma_f16(float* d, const uint32_t* a, const uint32_t* b) {
    asm volatile("mma.sync.aligned.m16n8k16.row.col.f32.f16.f16.f32 "
                 "{%0,%1,%2,%3}, {%4,%5,%6,%7}, {%8,%9}, {%0,%1,%2,%3};"
                 : "+f"(d[0]), "+f"(d[1]), "+f"(d[2]), "+f"(d[3])
                 : "r"(a[0]), "r"(a[1]), "r"(a[2]), "r"(a[3]), "r"(b[0]), "r"(b[1]));
}

// ======================= K1: stats + fp16 A plane =========================
__global__ void __launch_bounds__(256) k1_stats(const float* __restrict__ in) {
    int bid = blockIdx.x;
    int spk = bid >> 3, part = bid & 7;
    int tid = threadIdx.x, w = tid >> 5, l = tid & 31;
    __shared__ float qp[8][8];

    float c0 = 0.f, c1 = 0.f, c2 = 0.f, c3 = 0.f;
    size_t rowbase = ((size_t)spk * MUTT + part * 8) * DDIM;
    const float4* src = (const float4*)(in + rowbase);

    #pragma unroll
    for (int r = 0; r < 8; r++) {
        float4 v = src[r * (DDIM / 4) + tid];
        c0 += v.x; c1 += v.y; c2 += v.z; c3 += v.w;
        float q = v.x * v.x + v.y * v.y + v.z * v.z + v.w * v.w;
        #pragma unroll
        for (int o = 16; o; o >>= 1) q += __shfl_down_sync(0xffffffffu, q, o);
        if (l == 0) qp[r][w] = q;

        union { __half2 h2[2]; uint2 u; } ph;
        ph.h2[0] = __floats2half2_rn(v.x, v.y);
        ph.h2[1] = __floats2half2_rn(v.z, v.w);
        *(uint2*)(g_a + rowbase + (size_t)r * DDIM + (size_t)tid * 4) = ph.u;
    }
    __syncthreads();
    if (tid < 8) {
        float s = 0.f;
        #pragma unroll
        for (int i = 0; i < 8; i++) s += qp[tid][i];
        g_q[spk * MUTT + part * 8 + tid] = s;
    }
    float4 s4; s4.x = c0; s4.y = c1; s4.z = c2; s4.w = c3;
    ((float4*)g_psum)[(size_t)bid * (DDIM / 4) + tid] = s4;
}

// ======================= K2: centers (fp16) ===============================
__global__ void __launch_bounds__(256) k2_center() {
    int spk = blockIdx.x, tid = threadIdx.x;
    int w = tid >> 5, l = tid & 31;
    __shared__ float wp[8];
    float4 s4 = make_float4(0.f, 0.f, 0.f, 0.f);
    #pragma unroll
    for (int p = 0; p < 8; p++) {
        float4 t = ((const float4*)g_psum)[(size_t)(spk * 8 + p) * (DDIM / 4) + tid];
        s4.x += t.x; s4.y += t.y; s4.z += t.z; s4.w += t.w;
    }
    float4 m;
    m.x = s4.x * 0.015625f; m.y = s4.y * 0.015625f;
    m.z = s4.z * 0.015625f; m.w = s4.w * 0.015625f;
    float p = m.x * m.x + m.y * m.y + m.z * m.z + m.w * m.w;
    #pragma unroll
    for (int o = 16; o; o >>= 1) p += __shfl_down_sync(0xffffffffu, p, o);
    if (l == 0) wp[w] = p;
    __syncthreads();
    float ms = 0.f;
    #pragma unroll
    for (int i = 0; i < 8; i++) ms += wp[i];
    float r = 1.f / sqrtf(fmaxf(ms, 1e-12f));

    union { __half2 h2[2]; uint2 u; } ph;
    ph.h2[0] = __floats2half2_rn(m.x * r, m.y * r);
    ph.h2[1] = __floats2half2_rn(m.z * r, m.w * r);
    *(uint2*)(g_b + (size_t)spk * DDIM + (size_t)tid * 4) = ph.u;

    if (tid == 0) {
        g_L[spk]  = 64.f * sqrtf(ms);
        g_L2[spk] = 4096.f * ms;
    }
}

// ======================= K3: fp16 HMMA GEMM, 148 variable-M CTAs ==========
// 148 CTAs; CTA i covers NT(i) row-tiles of 16 (NT = 7 for i<136 else 6).
// 8 warps: 1(M) x 8(N); warp = full CTA rows x 32 cols. BK=32, 4-stage ring.
#define ROWB 80
#define NTMAX 7
#define A_OFF 0
#define B_OFF (NTMAX * 16 * ROWB)                 // 8960
#define ST_STRIDE (B_OFF + 256 * ROWB)            // 8960 + 20480 = 29440
#define K3_SMEM (4 * ST_STRIDE)                   // 117760
#define CSPLIT 136                                // CTAs with 7 tiles

static __device__ __forceinline__ void k3_loads(uint32_t sm, int st, int kst, int tid,
                                                int row0, int nrows) {
    uint32_t sb = sm + (uint32_t)st * ST_STRIDE;
    const char* ap = (const char*)g_a;
    const char* bp = (const char*)g_b;
    size_t kb = (size_t)kst * 64;   // byte offset within 2048-byte row
    // A: nrows x 64B -> nrows*4 chunks
    #pragma unroll
    for (int i = 0; i < 2; i++) {
        int c = tid + i * 256;
        if (c < nrows * 4) {
            int row = c >> 2; uint32_t sub = (uint32_t)(c & 3) * 16u;
            size_t go = ((size_t)(row0 + row)) * 2048 + kb + sub;
            cp16(sb + A_OFF + (uint32_t)row * ROWB + sub, ap + go);
        }
    }
    // B: 256 rows x 64B -> 1024 chunks, 4/thread
    #pragma unroll
    for (int i = 0; i < 4; i++) {
        int c = tid + i * 256;
        int row = c >> 2; uint32_t sub = (uint32_t)(c & 3) * 16u;
        size_t go = (size_t)row * 2048 + kb + sub;
        cp16(sb + B_OFF + (uint32_t)row * ROWB + sub, bp + go);
    }
}

template <int NT>
static __device__ __forceinline__ void k3_body(uint32_t sm, int tid, int row0,
                                               const float* w_p, const float* b_p,
                                               float* out) {
    int wid = tid >> 5, lane = tid & 31;
    const int nrows = NT * 16;

    uint32_t aoff[NT], boff[2];
    {
        uint32_t ars = (uint32_t)(lane & 15);
        uint32_t acs = (uint32_t)(lane >> 4) * 16u;
        uint32_t brs = (uint32_t)((lane & 7) + ((lane >> 4) << 3));
        uint32_t bcs = (uint32_t)((lane >> 3) & 1) * 16u;
        #pragma unroll
        for (int mt = 0; mt < NT; mt++)
            aoff[mt] = (uint32_t)(mt * 16 + ars) * ROWB + acs;
        #pragma unroll
        for (int np = 0; np < 2; np++)
            boff[np] = (uint32_t)(wid * 32 + np * 16 + brs) * ROWB + bcs;
    }

    float acc[NT][4][4];
    #pragma unroll
    for (int mt = 0; mt < NT; mt++)
        #pragma unroll
        for (int nt = 0; nt < 4; nt++)
            #pragma unroll
            for (int i = 0; i < 4; i++) acc[mt][nt][i] = 0.f;

    k3_loads(sm, 0, 0, tid, row0, nrows); cp_commit();
    k3_loads(sm, 1, 1, tid, row0, nrows); cp_commit();
    k3_loads(sm, 2, 2, tid, row0, nrows); cp_commit();

    #pragma unroll 1
    for (int k = 0; k < 32; k++) {
        int s = k & 3;
        if (k <= 29) cp_wait<2>(); else if (k == 30) cp_wait<1>(); else cp_wait<0>();
        __syncthreads();
        if (k + 3 < 32) {
            k3_loads(sm, (k + 3) & 3, k + 3, tid, row0, nrows);
            cp_commit();
        }
        uint32_t sb = sm + (uint32_t)s * ST_STRIDE;

        #pragma unroll
        for (int ks = 0; ks < 2; ks++) {
            uint32_t kb = (uint32_t)ks * 32u;
            uint32_t a[NT][4], b[4][2];
            #pragma unroll
            for (int np = 0; np < 2; np++) {
                uint32_t t[4];
                ldsm4(t, sb + B_OFF + boff[np] + kb);
                b[2 * np][0] = t[0]; b[2 * np][1] = t[1];
                b[2 * np + 1][0] = t[2]; b[2 * np + 1][1] = t[3];
            }
            #pragma unroll
            for (int mt = 0; mt < NT; mt++)
                ldsm4(a[mt], sb + A_OFF + aoff[mt] + kb);
            #pragma unroll
            for (int mt = 0; mt < NT; mt++)
                #pragma unroll
                for (int nt = 0; nt < 4; nt++)
                    mma_f16(acc[mt][nt], a[mt], b[nt]);
        }
    }

    // ---- fused epilogue ----
    float W = w_p[0], Bb = b_p[0];
    #pragma unroll
    for (int mt = 0; mt < NT; mt++) {
        int r0 = row0 + mt * 16 + (lane >> 2);
        int r1 = r0 + 8;
        int j0 = r0 >> 6, j1 = r1 >> 6;
        float q0 = g_q[r0], q1 = g_q[r1];
        float La = g_L[j0], L2a = g_L2[j0];
        float Lb = g_L[j1], L2b = g_L2[j1];
        #pragma unroll
        for (int nt = 0; nt < 4; nt++) {
            int c = wid * 32 + nt * 8 + (lane & 3) * 2;
            float v0 = acc[mt][nt][0], v1 = acc[mt][nt][1];
            float v2 = acc[mt][nt][2], v3 = acc[mt][nt][3];
            if (c == j0 || c + 1 == j0) {
                float g = (c == j0) ? v0 : v1;
                float sv = g * La;
                float dg = (sv - q0) / sqrtf(fmaxf(L2a - 2.f * sv + q0, 1e-12f));
                if (c == j0) v0 = dg; else v1 = dg;
            }
            if (c == j1 || c + 1 == j1) {
                float g = (c == j1) ? v2 : v3;
                float sv = g * Lb;
                float dg = (sv - q1) / sqrtf(fmaxf(L2b - 2.f * sv + q1, 1e-12f));
                if (c == j1) v2 = dg; else v3 = dg;
            }
            float2 o0, o1;
            o0.x = W * v0 + Bb; o0.y = W * v1 + Bb;
            o1.x = W * v2 + Bb; o1.y = W * v3 + Bb;
            *(float2*)(out + (size_t)r0 * 256 + c) = o0;
            *(float2*)(out + (size_t)r1 * 256 + c) = o1;
        }
    }
}

__global__ void __launch_bounds__(256, 1) k3_gemm(const float* __restrict__ w_p,
                                                  const float* __restrict__ b_p,
                                                  float* __restrict__ out) {
    extern __shared__ char smem[];
    uint32_t sm = smem_u32(smem);
    int tid = threadIdx.x, cta = blockIdx.x;
    if (cta < CSPLIT) {
        int row0 = cta * 112;
        k3_body<7>(sm, tid, row0, w_p, b_p, out);
    } else {
        int row0 = CSPLIT * 112 + (cta - CSPLIT) * 96;
        k3_body<6>(sm, tid, row0, w_p, b_p, out);
    }
}

// ======================= launch ===========================================
extern "C" void kernel_launch(void* const* d_in, const int* in_sizes, int n_in,
                              void* d_out, int out_size) {
    const float* in = (const float*)d_in[0];
    const float* w  = (const float*)d_in[1];
    const float* b  = (const float*)d_in[2];
    float* out = (float*)d_out;
    (void)in_sizes; (void)n_in; (void)out_size;

    cudaFuncSetAttribute(k3_gemm, cudaFuncAttributeMaxDynamicSharedMemorySize, K3_SMEM);

    k1_stats<<<NSPK * 8, 256>>>(in);
    k2_center<<<NSPK, 256>>>();
    k3_gemm<<<148, 256, K3_SMEM>>>(w, b, out);
}

// round 8
// speedup vs baseline: 6.0217x; 1.0860x over previous
#include <cuda_runtime.h>
#include <cuda_fp16.h>
#include <stdint.h>

#define NSPK 256
#define MUTT 64
#define DDIM 1024
#define NROWS (NSPK*MUTT)   // 16384

// ---------------- device scratch (no dynamic allocation allowed) ---------
__device__ __half g_a[(size_t)NROWS * DDIM];     // 32 MB  (A, fp16)
__device__ __half g_b[NSPK * DDIM];              // 512 KB (B, fp16)
__device__ float  g_psum[8 * NSPK * DDIM];       // 8 MB (8 partials/speaker)
__device__ float  g_q[NROWS];
__device__ float  g_L[NSPK];
__device__ float  g_L2[NSPK];

// ---------------- helpers -------------------------------------------------
static __device__ __forceinline__ uint32_t smem_u32(const void* p) {
    uint32_t a;
    asm("{ .reg .u64 t; cvta.to.shared.u64 t, %1; cvt.u32.u64 %0, t; }" : "=r"(a) : "l"(p));
    return a;
}
static __device__ __forceinline__ void cp16(uint32_t d, const void* s) {
    asm volatile("cp.async.cg.shared.global [%0], [%1], 16;\n" :: "r"(d), "l"(s));
}
static __device__ __forceinline__ void cp_commit() {
    asm volatile("cp.async.commit_group;\n" ::: "memory");
}
template <int N> static __device__ __forceinline__ void cp_wait() {
    asm volatile("cp.async.wait_group %0;\n" :: "n"(N) : "memory");
}
static __device__ __forceinline__ void ldsm4(uint32_t* r, uint32_t addr) {
    asm volatile("ldmatrix.sync.aligned.m8n8.x4.shared.b16 {%0,%1,%2,%3}, [%4];"
                 : "=r"(r[0]), "=r"(r[1]), "=r"(r[2]), "=r"(r[3]) : "r"(addr));
}
static __device__ __forceinline__ void mma_f16(float* d, const uint32_t* a, const uint32_t* b) {
    asm volatile("mma.sync.aligned.m16n8k16.row.col.f32.f16.f16.f32 "
                 "{%0,%1,%2,%3}, {%4,%5,%6,%7}, {%8,%9}, {%0,%1,%2,%3};"
                 : "+f"(d[0]), "+f"(d[1]), "+f"(d[2]), "+f"(d[3])
                 : "r"(a[0]), "r"(a[1]), "r"(a[2]), "r"(a[3]), "r"(b[0]), "r"(b[1]));
}

// ======================= K1: stats + fp16 A plane =========================
__global__ void __launch_bounds__(256) k1_stats(const float* __restrict__ in) {
    int bid = blockIdx.x;
    int spk = bid >> 3, part = bid & 7;
    int tid = threadIdx.x, w = tid >> 5, l = tid & 31;
    __shared__ float qp[8][8];

    float c0 = 0.f, c1 = 0.f, c2 = 0.f, c3 = 0.f;
    size_t rowbase = ((size_t)spk * MUTT + part * 8) * DDIM;
    const float4* src = (const float4*)(in + rowbase);

    #pragma unroll
    for (int r = 0; r < 8; r++) {
        float4 v = src[r * (DDIM / 4) + tid];
        c0 += v.x; c1 += v.y; c2 += v.z; c3 += v.w;
        float q = v.x * v.x + v.y * v.y + v.z * v.z + v.w * v.w;
        #pragma unroll
        for (int o = 16; o; o >>= 1) q += __shfl_down_sync(0xffffffffu, q, o);
        if (l == 0) qp[r][w] = q;

        union { __half2 h2[2]; uint2 u; } ph;
        ph.h2[0] = __floats2half2_rn(v.x, v.y);
        ph.h2[1] = __floats2half2_rn(v.z, v.w);
        *(uint2*)(g_a + rowbase + (size_t)r * DDIM + (size_t)tid * 4) = ph.u;
    }
    __syncthreads();
    if (tid < 8) {
        float s = 0.f;
        #pragma unroll
        for (int i = 0; i < 8; i++) s += qp[tid][i];
        g_q[spk * MUTT + part * 8 + tid] = s;
    }
    float4 s4; s4.x = c0; s4.y = c1; s4.z = c2; s4.w = c3;
    ((float4*)g_psum)[(size_t)bid * (DDIM / 4) + tid] = s4;
}

// ======================= K2: centers (fp16) ===============================
__global__ void __launch_bounds__(256) k2_center() {
    int spk = blockIdx.x, tid = threadIdx.x;
    int w = tid >> 5, l = tid & 31;
    __shared__ float wp[8];
    float4 s4 = make_float4(0.f, 0.f, 0.f, 0.f);
    #pragma unroll
    for (int p = 0; p < 8; p++) {
        float4 t = ((const float4*)g_psum)[(size_t)(spk * 8 + p) * (DDIM / 4) + tid];
        s4.x += t.x; s4.y += t.y; s4.z += t.z; s4.w += t.w;
    }
    float4 m;
    m.x = s4.x * 0.015625f; m.y = s4.y * 0.015625f;
    m.z = s4.z * 0.015625f; m.w = s4.w * 0.015625f;
    float p = m.x * m.x + m.y * m.y + m.z * m.z + m.w * m.w;
    #pragma unroll
    for (int o = 16; o; o >>= 1) p += __shfl_down_sync(0xffffffffu, p, o);
    if (l == 0) wp[w] = p;
    __syncthreads();
    float ms = 0.f;
    #pragma unroll
    for (int i = 0; i < 8; i++) ms += wp[i];
    float r = 1.f / sqrtf(fmaxf(ms, 1e-12f));

    union { __half2 h2[2]; uint2 u; } ph;
    ph.h2[0] = __floats2half2_rn(m.x * r, m.y * r);
    ph.h2[1] = __floats2half2_rn(m.z * r, m.w * r);
    *(uint2*)(g_b + (size_t)spk * DDIM + (size_t)tid * 4) = ph.u;

    if (tid == 0) {
        g_L[spk]  = 64.f * sqrtf(ms);
        g_L2[spk] = 4096.f * ms;
    }
}

// ======================= K3: fp16 HMMA GEMM, 148 variable-M CTAs ==========
// 148 CTAs; CTA i covers NT(i) row-tiles of 16 (NT = 7 for i<136 else 6).
// 8 warps: 1(M) x 8(N). BK=64 (128B/row), 3-stage ring, prefetch distance 2.
#define ROWB 144
#define NTMAX 7
#define A_OFF 0
#define B_OFF (NTMAX * 16 * ROWB)                 // 16128
#define ST_STRIDE (B_OFF + 256 * ROWB)            // 16128 + 36864 = 52992
#define K3_SMEM (3 * ST_STRIDE)                   // 158976
#define CSPLIT 136                                // CTAs with 7 tiles

static __device__ __forceinline__ void k3_loads(uint32_t sm, int st, int kst, int tid,
                                                int row0, int nrows) {
    uint32_t sb = sm + (uint32_t)st * ST_STRIDE;
    const char* ap = (const char*)g_a;
    const char* bp = (const char*)g_b;
    size_t kb = (size_t)kst * 128;  // BK=64 halves = 128 bytes within 2048-byte row
    // A: nrows x 128B -> nrows*8 chunks of 16B
    #pragma unroll
    for (int i = 0; i < 4; i++) {
        int c = tid + i * 256;
        if (c < nrows * 8) {
            int row = c >> 3; uint32_t sub = (uint32_t)(c & 7) * 16u;
            size_t go = ((size_t)(row0 + row)) * 2048 + kb + sub;
            cp16(sb + A_OFF + (uint32_t)row * ROWB + sub, ap + go);
        }
    }
    // B: 256 rows x 128B -> 2048 chunks, 8/thread
    #pragma unroll
    for (int i = 0; i < 8; i++) {
        int c = tid + i * 256;
        int row = c >> 3; uint32_t sub = (uint32_t)(c & 7) * 16u;
        size_t go = (size_t)row * 2048 + kb + sub;
        cp16(sb + B_OFF + (uint32_t)row * ROWB + sub, bp + go);
    }
}

template <int NT>
static __device__ __forceinline__ void k3_body(uint32_t sm, int tid, int row0,
                                               const float* w_p, const float* b_p,
                                               float* out) {
    int wid = tid >> 5, lane = tid & 31;
    const int nrows = NT * 16;

    uint32_t aoff[NT], boff[2];
    {
        uint32_t ars = (uint32_t)(lane & 15);
        uint32_t acs = (uint32_t)(lane >> 4) * 16u;
        uint32_t brs = (uint32_t)((lane & 7) + ((lane >> 4) << 3));
        uint32_t bcs = (uint32_t)((lane >> 3) & 1) * 16u;
        #pragma unroll
        for (int mt = 0; mt < NT; mt++)
            aoff[mt] = (uint32_t)(mt * 16 + ars) * ROWB + acs;
        #pragma unroll
        for (int np = 0; np < 2; np++)
            boff[np] = (uint32_t)(wid * 32 + np * 16 + brs) * ROWB + bcs;
    }

    float acc[NT][4][4];
    #pragma unroll
    for (int mt = 0; mt < NT; mt++)
        #pragma unroll
        for (int nt = 0; nt < 4; nt++)
            #pragma unroll
            for (int i = 0; i < 4; i++) acc[mt][nt][i] = 0.f;

    k3_loads(sm, 0, 0, tid, row0, nrows); cp_commit();
    k3_loads(sm, 1, 1, tid, row0, nrows); cp_commit();

    #pragma unroll 1
    for (int k = 0; k < 16; k++) {
        int s = k - (k / 3) * 3;              // k % 3
        if (k < 15) cp_wait<1>(); else cp_wait<0>();
        __syncthreads();
        if (k + 2 < 16) {
            int s2 = (k + 2) - ((k + 2) / 3) * 3;
            k3_loads(sm, s2, k + 2, tid, row0, nrows);
            cp_commit();
        }
        uint32_t sb = sm + (uint32_t)s * ST_STRIDE;

        #pragma unroll
        for (int ks = 0; ks < 4; ks++) {
            uint32_t kb = (uint32_t)ks * 32u;
            uint32_t a[NT][4], b[4][2];
            #pragma unroll
            for (int np = 0; np < 2; np++) {
                uint32_t t[4];
                ldsm4(t, sb + B_OFF + boff[np] + kb);
                b[2 * np][0] = t[0]; b[2 * np][1] = t[1];
                b[2 * np + 1][0] = t[2]; b[2 * np + 1][1] = t[3];
            }
            #pragma unroll
            for (int mt = 0; mt < NT; mt++)
                ldsm4(a[mt], sb + A_OFF + aoff[mt] + kb);
            #pragma unroll
            for (int mt = 0; mt < NT; mt++)
                #pragma unroll
                for (int nt = 0; nt < 4; nt++)
                    mma_f16(acc[mt][nt], a[mt], b[nt]);
        }
    }

    // ---- fused epilogue ----
    float W = w_p[0], Bb = b_p[0];
    #pragma unroll
    for (int mt = 0; mt < NT; mt++) {
        int r0 = row0 + mt * 16 + (lane >> 2);
        int r1 = r0 + 8;
        int j0 = r0 >> 6, j1 = r1 >> 6;
        float q0 = g_q[r0], q1 = g_q[r1];
        float La = g_L[j0], L2a = g_L2[j0];
        float Lb = g_L[j1], L2b = g_L2[j1];
        #pragma unroll
        for (int nt = 0; nt < 4; nt++) {
            int c = wid * 32 + nt * 8 + (lane & 3) * 2;
            float v0 = acc[mt][nt][0], v1 = acc[mt][nt][1];
            float v2 = acc[mt][nt][2], v3 = acc[mt][nt][3];
            if (c == j0 || c + 1 == j0) {
                float g = (c == j0) ? v0 : v1;
                float sv = g * La;
                float dg = (sv - q0) / sqrtf(fmaxf(L2a - 2.f * sv + q0, 1e-12f));
                if (c == j0) v0 = dg; else v1 = dg;
            }
            if (c == j1 || c + 1 == j1) {
                float g = (c == j1) ? v2 : v3;
                float sv = g * Lb;
                float dg = (sv - q1) / sqrtf(fmaxf(L2b - 2.f * sv + q1, 1e-12f));
                if (c == j1) v2 = dg; else v3 = dg;
            }
            float2 o0, o1;
            o0.x = W * v0 + Bb; o0.y = W * v1 + Bb;
            o1.x = W * v2 + Bb; o1.y = W * v3 + Bb;
            *(float2*)(out + (size_t)r0 * 256 + c) = o0;
            *(float2*)(out + (size_t)r1 * 256 + c) = o1;
        }
    }
}

__global__ void __launch_bounds__(256, 1) k3_gemm(const float* __restrict__ w_p,
                                                  const float* __restrict__ b_p,
                                                  float* __restrict__ out) {
    extern __shared__ char smem[];
    uint32_t sm = smem_u32(smem);
    int tid = threadIdx.x, cta = blockIdx.x;
    if (cta < CSPLIT) {
        int row0 = cta * 112;
        k3_body<7>(sm, tid, row0, w_p, b_p, out);
    } else {
        int row0 = CSPLIT * 112 + (cta - CSPLIT) * 96;
        k3_body<6>(sm, tid, row0, w_p, b_p, out);
    }
}

// ======================= launch ===========================================
extern "C" void kernel_launch(void* const* d_in, const int* in_sizes, int n_in,
                              void* d_out, int out_size) {
    const float* in = (const float*)d_in[0];
    const float* w  = (const float*)d_in[1];
    const float* b  = (const float*)d_in[2];
    float* out = (float*)d_out;
    (void)in_sizes; (void)n_in; (void)out_size;

    cudaFuncSetAttribute(k3_gemm, cudaFuncAttributeMaxDynamicSharedMemorySize, K3_SMEM);

    k1_stats<<<NSPK * 8, 256>>>(in);
    k2_center<<<NSPK, 256>>>();
    k3_gemm<<<148, 256, K3_SMEM>>>(w, b, out);
}